// round 7
// baseline (speedup 1.0000x reference)
#include <cuda_runtime.h>
#include <math.h>

// Problem constants
#define B_    512
#define T_    80
#define DENC  1024
#define DF    512
#define DW    512
#define H_    512
#define G4    2048   // 4*H
#define KX    1024   // DF + H (step GEMM K)

typedef unsigned long long ull;

// ---------------- packed f32x2 helpers (sm_103a FFMA2 path) ----------------
__device__ __forceinline__ ull pack2(float x) {
    ull r;
    asm("mov.b64 %0, {%1, %1};" : "=l"(r) : "r"(__float_as_uint(x)));
    return r;
}
__device__ __forceinline__ void fma2(ull& d, ull a, ull b) {
    asm("fma.rn.f32x2 %0, %1, %2, %0;" : "+l"(d) : "l"(a), "l"(b));
}
__device__ __forceinline__ float lo2(ull v) { return __uint_as_float((unsigned)v); }
__device__ __forceinline__ float hi2(ull v) { return __uint_as_float((unsigned)(v >> 32)); }

// ---------------- device scratch (no allocations allowed) ----------------
__device__ float g_feats[(size_t)B_ * T_ * DF];   // [B*T, DF], row m = b*T + t  (~84MB)
__device__ float g_WpT[DF * DENC];                // W_proj transposed [DF, DENC]
__device__ float g_word[B_ * DW];                 // gathered start embeddings
__device__ float g_bsum[G4];                      // b_ih + b_hh
__device__ float g_Gword[B_ * G4];                // word @ W_ih[:,512:]^T + bsum
__device__ float g_gates[B_ * G4];                // per-step gates
__device__ float g_h[B_ * H_];
__device__ float g_c[B_ * H_];

// ---------------- generic NT GEMM with K-split sources ----------------
// C[m][n] = sum_k A(k)[m,k'] * B(k)[n,k'] (+ bias[n]) (+ D[m][n])
// A/B each have two source pointers; source 0 covers k < kSplit, source 1 covers
// k >= kSplit (with k' = k - kSplit). kSplit must be a multiple of BK.
// All dims must divide the tile sizes exactly (true for all uses here).
template<int BM, int BN, int THREADS>
__global__ void __launch_bounds__(THREADS)
gemm_nt(int K, int kSplit,
        const float* __restrict__ A0, int lda0,
        const float* __restrict__ A1, int lda1,
        const float* __restrict__ Bm0, int ldb0,
        const float* __restrict__ Bm1, int ldb1,
        const float* __restrict__ bias,
        const float* __restrict__ Dm, int ldd,
        float* __restrict__ C, int ldc)
{
    constexpr int BK = 16, TM = 8, TN = 8;
    constexpr int TXN = BN / TN;                 // threads along n (=16)
    constexpr int A_LD = BM * BK / (4 * THREADS);
    constexpr int B_LD = BN * BK / (4 * THREADS);
    static_assert(TXN * (BM / TM) == THREADS, "thread tiling mismatch");

    __shared__ float As[2][BK][BM + 4];          // k-major, m contiguous
    __shared__ float Bs[2][BK][BN + 4];          // k-major, n contiguous

    const int tid = threadIdx.x;
    const int tx  = tid % TXN;
    const int ty  = tid / TXN;
    const int mB  = blockIdx.y * BM;
    const int nB  = blockIdx.x * BN;

    float4 ra[A_LD], rb[B_LD];

    auto loadG = [&](int kt) {
        const int k0 = kt * BK;
        const float* Ap; int ldA;
        const float* Bp; int ldB;
        if (k0 < kSplit) { Ap = A0 + k0;            ldA = lda0;
                           Bp = Bm0 + k0;           ldB = ldb0; }
        else             { Ap = A1 + (k0 - kSplit); ldA = lda1;
                           Bp = Bm1 + (k0 - kSplit); ldB = ldb1; }
#pragma unroll
        for (int s = 0; s < A_LD; s++) {
            int idx = tid + s * THREADS; int row = idx >> 2; int kq = idx & 3;
            ra[s] = *reinterpret_cast<const float4*>(Ap + (size_t)(mB + row) * ldA + kq * 4);
        }
#pragma unroll
        for (int s = 0; s < B_LD; s++) {
            int idx = tid + s * THREADS; int row = idx >> 2; int kq = idx & 3;
            rb[s] = *reinterpret_cast<const float4*>(Bp + (size_t)(nB + row) * ldB + kq * 4);
        }
    };
    auto storeS = [&](int buf) {
#pragma unroll
        for (int s = 0; s < A_LD; s++) {
            int idx = tid + s * THREADS; int row = idx >> 2; int kq = idx & 3;
            As[buf][kq * 4 + 0][row] = ra[s].x;
            As[buf][kq * 4 + 1][row] = ra[s].y;
            As[buf][kq * 4 + 2][row] = ra[s].z;
            As[buf][kq * 4 + 3][row] = ra[s].w;
        }
#pragma unroll
        for (int s = 0; s < B_LD; s++) {
            int idx = tid + s * THREADS; int row = idx >> 2; int kq = idx & 3;
            Bs[buf][kq * 4 + 0][row] = rb[s].x;
            Bs[buf][kq * 4 + 1][row] = rb[s].y;
            Bs[buf][kq * 4 + 2][row] = rb[s].z;
            Bs[buf][kq * 4 + 3][row] = rb[s].w;
        }
    };

    ull acc[4][8];
#pragma unroll
    for (int i = 0; i < 4; i++)
#pragma unroll
        for (int j = 0; j < 8; j++) acc[i][j] = 0ull;

    const int mb = ty * TM, nb = tx * TN;

    loadG(0); storeS(0); __syncthreads();
    const int KT = K / BK;
    for (int kt = 0; kt < KT; ++kt) {
        const int cur = kt & 1;
        if (kt + 1 < KT) loadG(kt + 1);
#pragma unroll
        for (int kk = 0; kk < BK; kk++) {
            ulonglong2 av0 = *reinterpret_cast<const ulonglong2*>(&As[cur][kk][mb]);
            ulonglong2 av1 = *reinterpret_cast<const ulonglong2*>(&As[cur][kk][mb + 4]);
            ull a2[4] = { av0.x, av0.y, av1.x, av1.y };   // (m0,m1)(m2,m3)(m4,m5)(m6,m7)
            float4 b0 = *reinterpret_cast<const float4*>(&Bs[cur][kk][nb]);
            float4 b1 = *reinterpret_cast<const float4*>(&Bs[cur][kk][nb + 4]);
            ull bb[8] = { pack2(b0.x), pack2(b0.y), pack2(b0.z), pack2(b0.w),
                          pack2(b1.x), pack2(b1.y), pack2(b1.z), pack2(b1.w) };
#pragma unroll
            for (int i = 0; i < 4; i++)
#pragma unroll
                for (int j = 0; j < 8; j++) fma2(acc[i][j], a2[i], bb[j]);
        }
        if (kt + 1 < KT) storeS(cur ^ 1);
        __syncthreads();
    }

    // epilogue
#pragma unroll
    for (int i = 0; i < 4; i++) {
#pragma unroll
        for (int hh = 0; hh < 2; hh++) {
            const int m = mB + mb + 2 * i + hh;
            float* Cr = C + (size_t)m * ldc + nB + nb;
            const float* Dr = Dm ? (Dm + (size_t)m * ldd + nB + nb) : nullptr;
#pragma unroll
            for (int j = 0; j < 8; j++) {
                float v = hh ? hi2(acc[i][j]) : lo2(acc[i][j]);
                if (bias) v += bias[nB + nb + j];
                if (Dr)   v += Dr[j];
                Cr[j] = v;
            }
        }
    }
}

// ---------------- small prep kernels ----------------
__global__ void transpose_k(const float* __restrict__ in, float* __restrict__ out,
                            int R, int Ccols) {  // out[c][r] = in[r][c]
    __shared__ float tile[32][33];
    int r0 = blockIdx.y * 32, c0 = blockIdx.x * 32;
    for (int i = threadIdx.y; i < 32; i += 8)
        tile[i][threadIdx.x] = in[(size_t)(r0 + i) * Ccols + c0 + threadIdx.x];
    __syncthreads();
    for (int i = threadIdx.y; i < 32; i += 8)
        out[(size_t)(c0 + i) * R + r0 + threadIdx.x] = tile[threadIdx.x][i];
}

__global__ void gather_word_k(const float* __restrict__ emb, const int* __restrict__ ids,
                              float* __restrict__ word) {
    int b = blockIdx.x;
    int id = ids[b];
    const float4* src = reinterpret_cast<const float4*>(emb + (size_t)id * DW);
    float4* dst = reinterpret_cast<float4*>(word + (size_t)b * DW);
    for (int i = threadIdx.x; i < DW / 4; i += blockDim.x) dst[i] = src[i];
}

__global__ void bias_sum_k(const float* __restrict__ a, const float* __restrict__ b,
                           float* __restrict__ o) {
    int i = blockIdx.x * blockDim.x + threadIdx.x;
    if (i < G4) o[i] = a[i] + b[i];
}

__global__ void zero_hc_k(float* __restrict__ h, float* __restrict__ c) {
    int i = blockIdx.x * blockDim.x + threadIdx.x;
    if (i < B_ * H_) { h[i] = 0.f; c[i] = 0.f; }
}

// ---------------- LSTM cell (elementwise) ----------------
__global__ void lstm_cell_k(const float* __restrict__ gates,
                            float* __restrict__ h, float* __restrict__ c,
                            float* __restrict__ out, int t) {
    int idx = blockIdx.x * blockDim.x + threadIdx.x;   // < B*H
    if (idx >= B_ * H_) return;
    int b = idx >> 9;        // /512
    int n = idx & 511;
    const float* gr = gates + (size_t)b * G4;
    float gi = gr[n];
    float gf = gr[H_ + n];
    float gg = gr[2 * H_ + n];
    float go = gr[3 * H_ + n];
    float si = 1.f / (1.f + expf(-gi));
    float sf = 1.f / (1.f + expf(-gf));
    float so = 1.f / (1.f + expf(-go));
    float cn = sf * c[idx] + si * tanhf(gg);
    float hn = so * tanhf(cn);
    c[idx] = cn;
    h[idx] = hn;
    out[((size_t)b * T_ + t) * H_ + n] = hn;
}

// ---------------- launch ----------------
extern "C" void kernel_launch(void* const* d_in, const int* in_sizes, int n_in,
                              void* d_out, int out_size) {
    const float* enc   = (const float*)d_in[0];  // [B, T, DENC]
    const int*   sid   = (const int*)  d_in[1];  // [B]
    const float* Wproj = (const float*)d_in[2];  // [DENC, DF]
    const float* bproj = (const float*)d_in[3];  // [DF]
    const float* emb   = (const float*)d_in[4];  // [V, DW]
    const float* Wih   = (const float*)d_in[5];  // [4H, DF+DW]
    const float* Whh   = (const float*)d_in[6];  // [4H, H]
    const float* bih   = (const float*)d_in[7];  // [4H]
    const float* bhh   = (const float*)d_in[8];  // [4H]
    float* out = (float*)d_out;                  // [B, T, H]

    float *feats, *WpT, *word, *bsum, *Gword, *gates, *h, *c;
    cudaGetSymbolAddress((void**)&feats, g_feats);
    cudaGetSymbolAddress((void**)&WpT,   g_WpT);
    cudaGetSymbolAddress((void**)&word,  g_word);
    cudaGetSymbolAddress((void**)&bsum,  g_bsum);
    cudaGetSymbolAddress((void**)&Gword, g_Gword);
    cudaGetSymbolAddress((void**)&gates, g_gates);
    cudaGetSymbolAddress((void**)&h,     g_h);
    cudaGetSymbolAddress((void**)&c,     g_c);

    // prep
    transpose_k<<<dim3(DF / 32, DENC / 32), dim3(32, 8)>>>(Wproj, WpT, DENC, DF);
    gather_word_k<<<B_, 128>>>(emb, sid, word);
    bias_sum_k<<<G4 / 256, 256>>>(bih, bhh, bsum);
    zero_hc_k<<<(B_ * H_) / 256, 256>>>(h, c);

    // feats = enc @ W_proj + b_proj     (M = B*T = 40960, N = DF, K = DENC)
    gemm_nt<128, 128, 256><<<dim3(DF / 128, (B_ * T_) / 128), 256>>>(
        DENC, DENC,
        enc, DENC, enc, DENC,
        WpT, DENC, WpT, DENC,
        bproj, nullptr, 0, feats, DF);

    // Gword = word @ W_ih[:, DF:]^T + (b_ih + b_hh)   (M = B, N = 4H, K = DW)
    gemm_nt<128, 128, 256><<<dim3(G4 / 128, B_ / 128), 256>>>(
        DW, DW,
        word, DW, word, DW,
        Wih + DF, DF + DW, Wih + DF, DF + DW,
        bsum, nullptr, 0, Gword, G4);

    // recurrence: gates = [feat_t | h] @ [W_ih[:, :DF] | W_hh]^T + Gword
    for (int t = 0; t < T_; t++) {
        gemm_nt<64, 128, 128><<<dim3(G4 / 128, B_ / 64), 128>>>(
            KX, DF,
            feats + (size_t)t * DF, T_ * DF,   // A0: feat rows, stride T*DF
            h, H_,                             // A1: hidden state
            Wih, DF + DW,                      // B0: W_ih feature columns (k < DF)
            Whh, H_,                           // B1: W_hh (k >= DF)
            nullptr, Gword, G4, gates, G4);
        lstm_cell_k<<<(B_ * H_) / 256, 256>>>(gates, h, c, out, t);
    }
}